// round 5
// baseline (speedup 1.0000x reference)
#include <cuda_runtime.h>
#include <cstdint>

#define NV 100000
#define ME 50000
#define D  128
#define WMED (1.0f / 13.0f)

// ---------------- scratch (device globals; no runtime allocation) ----------------
__device__ float g_Y[(size_t)NV * D];   // Y (pre-scaled linear output)
__device__ float g_deg[NV];             // extra degree (actual deg = 1 + g_deg); memset 0
__device__ int   g_pair[ME];

// ---------------- helpers ----------------
__device__ __forceinline__ float4 f4add(float4 a, float4 b) {
    return make_float4(a.x + b.x, a.y + b.y, a.z + b.z, a.w + b.w);
}
__device__ __forceinline__ float4 f4scale(float4 a, float s) {
    return make_float4(a.x * s, a.y * s, a.z * s, a.w * s);
}
__device__ __forceinline__ void red_add_v4(float* p, float4 v) {
    asm volatile("red.global.add.v4.f32 [%0], {%1,%2,%3,%4};"
                 :: "l"(p), "f"(v.x), "f"(v.y), "f"(v.z), "f"(v.w) : "memory");
}
__device__ __forceinline__ float warp_sum(float v) {
#pragma unroll
    for (int o = 16; o > 0; o >>= 1) v += __shfl_xor_sync(0xffffffffu, v, o);
    return v;
}
__device__ __forceinline__ float rsqrt_ref(float dg) {
    float rs = rsqrtf(dg);
    return rs * (1.5f - 0.5f * dg * rs * rs);
}
__device__ __forceinline__ const int* pick_verts(const int* __restrict__ c0,
                                                 const int* __restrict__ c1) {
    bool c0_is_edges = (c0[0] == 0 && c0[1] == 0 && c0[8] == 1 && c0[9] == 1);
    return c0_is_edges ? c1 : c0;
}

// ================= GEMM: Y = X @ W + b via 3xTF32 mma.sync =================
__device__ __forceinline__ uint32_t to_tf32(float x) {
    uint32_t r;
    asm("cvt.rna.tf32.f32 %0, %1;" : "=r"(r) : "f"(x));
    return r;
}
__device__ __forceinline__ void split_tf32(float x, uint32_t& hi, uint32_t& lo) {
    hi = to_tf32(x);
    lo = to_tf32(x - __uint_as_float(hi));
}
__device__ __forceinline__ void mma_tf32(float* c, const uint32_t* a, const uint32_t* b) {
    asm volatile(
        "mma.sync.aligned.m16n8k8.row.col.f32.tf32.tf32.f32 "
        "{%0,%1,%2,%3}, {%4,%5,%6,%7}, {%8,%9}, {%0,%1,%2,%3};"
        : "+f"(c[0]), "+f"(c[1]), "+f"(c[2]), "+f"(c[3])
        : "r"(a[0]), "r"(a[1]), "r"(a[2]), "r"(a[3]), "r"(b[0]), "r"(b[1]));
}

#define SROW 132                                // padded row stride (floats)
#define SM_GEMM_TOT (2 * 128 * SROW * 4)        // 135168 bytes

__global__ void __launch_bounds__(256) k_gemm_tc(const float* __restrict__ X,
                                                 const float* __restrict__ Wm,
                                                 const float* __restrict__ bias) {
    extern __shared__ float smem[];
    float* sA = smem;                  // A[row][k], stride SROW
    float* sB = smem + 128 * SROW;     // B[n][k] = W[k][n], stride SROW
    const int tid  = threadIdx.x;
    const int wid  = tid >> 5;
    const int lane = tid & 31;
    const int g    = lane >> 2;        // group id 0..7
    const int t    = lane & 3;         // thread-in-group 0..3
    const int row0 = blockIdx.x * 128;
    const int wm   = (wid & 3) * 32;   // warp M offset (0/32/64/96)
    const int wn   = (wid >> 2) * 64;  // warp N offset (0/64)

    // ---- load A tile (128 x 128 fp32), float4 coalesced ----
#pragma unroll
    for (int i = 0; i < 16; i++) {
        int idx = tid + i * 256;       // 0..4095 float4s
        int row = idx >> 5, q = idx & 31;
        int gr = row0 + row;
        float4 v = make_float4(0.f, 0.f, 0.f, 0.f);
        if (gr < NV) v = *(const float4*)&X[(size_t)gr * D + q * 4];
        *(float4*)&sA[row * SROW + q * 4] = v;
    }
    // ---- load B = W^T: coalesced global read, scattered smem write ----
#pragma unroll
    for (int i = 0; i < 64; i++) {
        int idx = tid + i * 256;       // 0..16383
        int k = idx >> 7, n = idx & 127;
        sB[n * SROW + k] = Wm[(size_t)k * D + n];
    }
    __syncthreads();

    // ---- compute: 16 k-steps, per warp 2x8 mma tiles, 3 limb products each ----
    float acc[2][8][4];
#pragma unroll
    for (int mt = 0; mt < 2; mt++)
#pragma unroll
        for (int nt = 0; nt < 8; nt++)
#pragma unroll
            for (int j = 0; j < 4; j++) acc[mt][nt][j] = 0.f;

#pragma unroll
    for (int ks = 0; ks < 16; ks++) {
        const int k0 = ks * 8;
        uint32_t ah[2][4], al[2][4];
#pragma unroll
        for (int mt = 0; mt < 2; mt++) {
            int rb = wm + mt * 16;
            float x0 = sA[(rb + g) * SROW + k0 + t];
            float x1 = sA[(rb + g + 8) * SROW + k0 + t];
            float x2 = sA[(rb + g) * SROW + k0 + t + 4];
            float x3 = sA[(rb + g + 8) * SROW + k0 + t + 4];
            split_tf32(x0, ah[mt][0], al[mt][0]);
            split_tf32(x1, ah[mt][1], al[mt][1]);
            split_tf32(x2, ah[mt][2], al[mt][2]);
            split_tf32(x3, ah[mt][3], al[mt][3]);
        }
        uint32_t bh[8][2], bl[8][2];
#pragma unroll
        for (int nt = 0; nt < 8; nt++) {
            int nb = wn + nt * 8 + g;
            float y0 = sB[nb * SROW + k0 + t];
            float y1 = sB[nb * SROW + k0 + t + 4];
            split_tf32(y0, bh[nt][0], bl[nt][0]);
            split_tf32(y1, bh[nt][1], bl[nt][1]);
        }
#pragma unroll
        for (int mt = 0; mt < 2; mt++)
#pragma unroll
            for (int nt = 0; nt < 8; nt++) {
                mma_tf32(acc[mt][nt], ah[mt], bh[nt]);
                mma_tf32(acc[mt][nt], al[mt], bh[nt]);
                mma_tf32(acc[mt][nt], ah[mt], bl[nt]);
            }
    }
    __syncthreads();

    // ---- stage to smem (reuse sA region), then coalesced bias-add writeout ----
#pragma unroll
    for (int mt = 0; mt < 2; mt++)
#pragma unroll
        for (int nt = 0; nt < 8; nt++) {
            int r0 = wm + mt * 16 + g;
            int c0 = wn + nt * 8 + 2 * t;
            *(float2*)&sA[r0 * SROW + c0]       = make_float2(acc[mt][nt][0], acc[mt][nt][1]);
            *(float2*)&sA[(r0 + 8) * SROW + c0] = make_float2(acc[mt][nt][2], acc[mt][nt][3]);
        }
    __syncthreads();
#pragma unroll
    for (int i = 0; i < 16; i++) {
        int idx = tid + i * 256;
        int row = idx >> 5, q = idx & 31;
        int gr = row0 + row;
        if (gr >= NV) continue;
        float4 v = *(const float4*)&sA[row * SROW + q * 4];
        float4 bv = *(const float4*)&bias[q * 4];
        *(float4*)&g_Y[(size_t)gr * D + q * 4] = f4add(v, bv);
    }
}

// ---------------- K2: per-hyperedge argmax pair + degree atomics ----------------
__global__ void __launch_bounds__(256) k_edge(const int* __restrict__ c0,
                                              const int* __restrict__ c1) {
    int w    = (blockIdx.x * blockDim.x + threadIdx.x) >> 5;
    int lane = threadIdx.x & 31;
    if (w >= ME) return;
    const int* verts = pick_verts(c0, c1);

    int4 p0 = ((const int4*)(verts + w * 8))[0];
    int4 p1 = ((const int4*)(verts + w * 8))[1];
    int v[8] = {p0.x, p0.y, p0.z, p0.w, p1.x, p1.y, p1.z, p1.w};

    float4 f[8];
#pragma unroll
    for (int j = 0; j < 8; j++)
        f[j] = *(const float4*)&g_Y[(size_t)v[j] * D + lane * 4];

    float sq[8];
#pragma unroll
    for (int j = 0; j < 8; j++)
        sq[j] = warp_sum(f[j].x * f[j].x + f[j].y * f[j].y +
                         f[j].z * f[j].z + f[j].w * f[j].w);

    float best = -1e30f;
    int bu = 0, bv = 1;
#pragma unroll
    for (int j = 0; j < 8; j++) {
#pragma unroll
        for (int l = j + 1; l < 8; l++) {
            float d = warp_sum(f[j].x * f[l].x + f[j].y * f[l].y +
                               f[j].z * f[l].z + f[j].w * f[l].w);
            float d2 = sq[j] + sq[l] - 2.0f * d;
            if (d2 > best) { best = d2; bu = j; bv = l; }   // first-occurrence, row-major
        }
    }

    int myv = v[0];
#pragma unroll
    for (int j = 1; j < 8; j++) if (lane == j) myv = v[j];
    if (lane < 8) {
        float wd = (lane == bu || lane == bv) ? 7.0f * WMED : 2.0f * WMED;
        atomicAdd(&g_deg[myv], wd);
    }
    if (lane == 0) g_pair[w] = bu | (bv << 4);
}

// ---------------- K3: scatter graph-edge contributions (out starts at 0) ----------------
__global__ void __launch_bounds__(256) k_scatter(float* __restrict__ out,
                                                 const int* __restrict__ c0,
                                                 const int* __restrict__ c1) {
    int w    = (blockIdx.x * blockDim.x + threadIdx.x) >> 5;
    int lane = threadIdx.x & 31;
    if (w >= ME) return;
    const int* verts = pick_verts(c0, c1);

    int4 p0 = ((const int4*)(verts + w * 8))[0];
    int4 p1 = ((const int4*)(verts + w * 8))[1];
    int v[8] = {p0.x, p0.y, p0.z, p0.w, p1.x, p1.y, p1.z, p1.w};

    int myv = v[0];
#pragma unroll
    for (int j = 1; j < 8; j++) if (lane == j) myv = v[j];
    float mydinv = 0.f;
    if (lane < 8) mydinv = rsqrt_ref(1.0f + g_deg[myv]);
    float dv[8];
#pragma unroll
    for (int j = 0; j < 8; j++) dv[j] = __shfl_sync(0xffffffffu, mydinv, j);

    int code = g_pair[w];
    int bu = code & 15, bv = code >> 4;

    float4 su = make_float4(0.f, 0.f, 0.f, 0.f);
    float4 sv = su;
    float4 smed = su;
#pragma unroll
    for (int j = 0; j < 8; j++) {
        float4 f = *(const float4*)&g_Y[(size_t)v[j] * D + lane * 4];
        f = f4scale(f, dv[j]);                      // Xs row
        if (j == bu)      su = f;
        else if (j == bv) sv = f;
        else              smed = f4add(smed, f);
    }

    float4 Au = f4scale(f4add(sv, smed), WMED);
    float4 Av = f4scale(f4add(su, smed), WMED);
    float4 Am = f4scale(f4add(su, sv),   WMED);

#pragma unroll
    for (int j = 0; j < 8; j++) {
        float4 val = (j == bu) ? Au : ((j == bv) ? Av : Am);
        red_add_v4(&out[(size_t)v[j] * D + lane * 4], val);
    }
}

// ---------------- K4: out = relu((out + Y*dinv) * dinv) ----------------
__global__ void k_final(float* __restrict__ out) {
    int i = blockIdx.x * blockDim.x + threadIdx.x;
    if (i >= NV * (D / 4)) return;
    int row = i >> 5;
    float r = rsqrt_ref(1.0f + g_deg[row]);
    float4 o = ((float4*)out)[i];
    float4 y = ((const float4*)g_Y)[i];
    o.x = fmaxf((o.x + y.x * r) * r, 0.f);
    o.y = fmaxf((o.y + y.y * r) * r, 0.f);
    o.z = fmaxf((o.z + y.z * r) * r, 0.f);
    o.w = fmaxf((o.w + y.w * r) * r, 0.f);
    ((float4*)out)[i] = o;
}

// ---------------- launcher ----------------
extern "C" void kernel_launch(void* const* d_in, const int* in_sizes, int n_in,
                              void* d_out, int out_size) {
    const float* X = nullptr;
    const float* W = nullptr;
    const float* b = nullptr;
    const int* c0 = nullptr;
    const int* c1 = nullptr;

    for (int i = 0; i < n_in; i++) {
        int s = in_sizes[i];
        if (s == NV * D)        X = (const float*)d_in[i];
        else if (s == D * D)    W = (const float*)d_in[i];
        else if (s == D)        b = (const float*)d_in[i];
        else if (s == ME * 8) { if (!c0) c0 = (const int*)d_in[i]; else c1 = (const int*)d_in[i]; }
    }
    float* out = (float*)d_out;

    void* degPtr = nullptr;
    cudaGetSymbolAddress(&degPtr, g_deg);
    cudaFuncSetAttribute(k_gemm_tc, cudaFuncAttributeMaxDynamicSharedMemorySize, SM_GEMM_TOT);

    cudaMemsetAsync(degPtr, 0, (size_t)NV * sizeof(float), 0);
    cudaMemsetAsync(out, 0, (size_t)NV * D * sizeof(float), 0);
    k_gemm_tc<<<(NV + 127) / 128, 256, SM_GEMM_TOT>>>(X, W, b);
    k_edge<<<(ME * 32 + 255) / 256, 256>>>(c0, c1);
    k_scatter<<<(ME * 32 + 255) / 256, 256>>>(out, c0, c1);
    k_final<<<(NV * (D / 4) + 255) / 256, 256>>>(out);
}